// round 15
// baseline (speedup 1.0000x reference)
#include <cuda_runtime.h>
#include <cuda_fp16.h>
#include <cstdint>

#define Hc 128
#define Wc 128
#define Cc 64
#define COUTc 64
#define Bc 4
#define NPIX (Bc*Hc*Wc)

// ------------------------------ scratch ------------------------------------
__device__ uint4  g_xH4[NPIX*8];        // NHWC fp16 input (8 uint4 = 64c/px)
__device__ uint4  g_wH4[9*512];         // main weights fp16 [tap][c64][co64]
__device__ uint4  g_owH4[9*192];        // offset weights fp16 [tap][c64][o24]

// ------------------------------ helpers ------------------------------------
__device__ __forceinline__ void mma16(float* d, const uint32_t* a,
                                      uint32_t b0, uint32_t b1) {
    asm volatile(
        "mma.sync.aligned.m16n8k16.row.col.f32.f16.f16.f32 "
        "{%0,%1,%2,%3}, {%4,%5,%6,%7}, {%8,%9}, {%0,%1,%2,%3};"
        : "+f"(d[0]), "+f"(d[1]), "+f"(d[2]), "+f"(d[3])
        : "r"(a[0]), "r"(a[1]), "r"(a[2]), "r"(a[3]), "r"(b0), "r"(b1));
}
__device__ __forceinline__ void ldsm_x4(uint32_t* r, uint32_t a) {
    asm volatile("ldmatrix.sync.aligned.m8n8.x4.shared.b16 {%0,%1,%2,%3}, [%4];"
        : "=r"(r[0]), "=r"(r[1]), "=r"(r[2]), "=r"(r[3]) : "r"(a));
}
__device__ __forceinline__ void ldsm_x4t(uint32_t* r, uint32_t a) {
    asm volatile("ldmatrix.sync.aligned.m8n8.x4.trans.shared.b16 {%0,%1,%2,%3}, [%4];"
        : "=r"(r[0]), "=r"(r[1]), "=r"(r[2]), "=r"(r[3]) : "r"(a));
}
__device__ __forceinline__ void ldsm_x2t(uint32_t* r, uint32_t a) {
    asm volatile("ldmatrix.sync.aligned.m8n8.x2.trans.shared.b16 {%0,%1}, [%2];"
        : "=r"(r[0]), "=r"(r[1]) : "r"(a));
}
__device__ __forceinline__ void cp_async16(uint32_t saddr, const void* gaddr) {
    asm volatile("cp.async.cg.shared.global [%0], [%1], 16;"
        :: "r"(saddr), "l"(gaddr) : "memory");
}
#define CP_COMMIT() asm volatile("cp.async.commit_group;" ::: "memory")
#define CP_WAIT0()  asm volatile("cp.async.wait_group 0;" ::: "memory")

// ---------------------------------------------------------------------------
// Kernel 1: prep. blocks 0..511: NCHW->NHWC fp16 transpose; 512+: weights.
// ---------------------------------------------------------------------------
__global__ void __launch_bounds__(256) prep_kernel(
    const float* __restrict__ x, const float* __restrict__ w,
    const float* __restrict__ ow)
{
    int bid = blockIdx.x, tid = threadIdx.x;
    if (bid < 512) {
        __shared__ float4 sm4[2048];
        int b = bid >> 7, y = bid & 127;
        const float4* xin = (const float4*)x;
        #pragma unroll
        for (int i = 0; i < 8; ++i) {
            int j4 = tid + 256 * i;
            int c = j4 >> 5, x4 = j4 & 31;
            int key = (c ^ (c >> 3)) & 7;
            sm4[c * 32 + (x4 ^ key)] =
                xin[((size_t)(b * Cc + c) * Hc + y) * 32 + x4];
        }
        __syncthreads();
        const float* smf = (const float*)sm4;
        #pragma unroll
        for (int i = 0; i < 4; ++i) {
            int j = tid + 256 * i;
            int grp = j & 7, px = j >> 3;
            float f[8];
            #pragma unroll
            for (int e = 0; e < 8; ++e) {
                int c = grp * 8 + e;
                int key = (c ^ (c >> 3)) & 7;
                f[e] = smf[c * 128 + 4 * ((px >> 2) ^ key) + (px & 3)];
            }
            uint4 r; half2* hr = (half2*)&r;
            hr[0] = __floats2half2_rn(f[0], f[1]);
            hr[1] = __floats2half2_rn(f[2], f[3]);
            hr[2] = __floats2half2_rn(f[4], f[5]);
            hr[3] = __floats2half2_rn(f[6], f[7]);
            g_xH4[((size_t)(b * Hc + y) * Wc + px) * 8 + grp] = r;
        }
    } else {
        int t = (bid - 512) * 256 + tid;
        half* wh = (half*)g_wH4;                    // [tap][c][co]
        for (int idx = t; idx < 9 * 64 * 64; idx += 36 * 256) {
            int tap = idx >> 12, r = idx & 4095;
            int c = r >> 6, co = r & 63;
            wh[idx] = __float2half(w[(co * Cc + c) * 9 + tap]);
        }
        half* oh = (half*)g_owH4;                   // [tap][c][24]
        for (int idx = t; idx < 9 * 64 * 24; idx += 36 * 256) {
            int tap = idx / 1536;
            int r = idx - tap * 1536;
            int c = r / 24, o = r - c * 24;
            oh[idx] = (o < 18) ? __float2half(ow[(o * Cc + c) * 9 + tap])
                               : __float2half(0.f);
        }
    }
}

// ---------------------------------------------------------------------------
// Kernel 2: FUSED offset conv + sampling + fp16 mma GEMM.
// Block = 1 image row (128 px) x 64 co, 512 THREADS (16 warps), 2 blocks/SM
// -> 32 warps/SM (vs 24) AND tail waste 13.5% (vs 42%). Warp tile 16px x 32co
// (16 acc regs) -> fits 64-reg cap without spills.
// smem words: patch[2][128][36] @0 (9216) | wsm[2][64][36] @9216 (4608)
//             offs[9][128]x2 @13824 (2304) | coordbuf[2][128]x8 @16128 (2048)
// total 18176 words = 72704 B
// ---------------------------------------------------------------------------
#define SM_OFFS 13824
#define SM_CB   16128
__device__ __forceinline__ void compute_coords(
    int k, int p, int y, int b, const float2* offs, uint4* cwh, int4* ci)
{
    float2 d2 = offs[k * 128 + p];
    int ky = k / 3, kx = k - ky * 3;
    float py  = (float)(y - 1 + ky) + d2.x;
    float pxx = (float)(p - 1 + kx) + d2.y;
    float fy = floorf(py), fx = floorf(pxx);
    float ly = py - fy, lx = pxx - fx;
    int y0 = (int)fy, xq = (int)fx;
    bool vy0 = (y0 >= 0) & (y0 < Hc);
    bool vy1 = (y0 + 1 >= 0) & (y0 + 1 < Hc);
    bool vx0 = (xq >= 0) & (xq < Wc);
    bool vx1 = (xq + 1 >= 0) & (xq + 1 < Wc);
    float w00 = (1.f - ly) * (1.f - lx) * (float)(vy0 && vx0);
    float w01 = (1.f - ly) * lx         * (float)(vy0 && vx1);
    float w10 = ly * (1.f - lx)         * (float)(vy1 && vx0);
    float w11 = ly * lx                 * (float)(vy1 && vx1);
    int yc0 = min(max(y0, 0), Hc - 1);
    int yc1 = min(max(y0 + 1, 0), Hc - 1);
    int xc0 = min(max(xq, 0), Wc - 1);
    int xc1 = min(max(xq + 1, 0), Wc - 1);
    int r0 = (b * Hc + yc0) * Wc, r1 = (b * Hc + yc1) * Wc;
    ci[p] = make_int4((r0 + xc0) * 8, (r0 + xc1) * 8,
                      (r1 + xc0) * 8, (r1 + xc1) * 8);
    uint4 wpk; half2* hp = (half2*)&wpk;
    hp[0] = __floats2half2_rn(w00, w00);
    hp[1] = __floats2half2_rn(w01, w01);
    hp[2] = __floats2half2_rn(w10, w10);
    hp[3] = __floats2half2_rn(w11, w11);
    cwh[p] = wpk;
}

__global__ void __launch_bounds__(512, 2) dcn_fused_kernel(
    const float* __restrict__ ob, const float* __restrict__ bias,
    float* __restrict__ out)
{
    extern __shared__ uint32_t smw[];
    uint32_t sb = (uint32_t)__cvta_generic_to_shared(smw);

    int tid = threadIdx.x, warp = tid >> 5, lane = tid & 31;
    int g = lane >> 2, tg = lane & 3;
    int l = lane & 7, h8 = (lane >> 3) & 1, kh = (lane >> 4) & 1;
    int m = lane >> 3;
    int blk = blockIdx.x, b = blk >> 7, y = blk & 127;

    // ======================= Phase A: offset conv ==========================
    // 16 warps: warps 0-7 -> m-tile (warp) x cols 0-15 (2 n-tiles)
    //           warps 8-15 -> m-tile (warp-8) x cols 16-23 (1 n-tile)
    {
        int amt = warp & 7;
        bool hi = warp >= 8;
        uint32_t a_lane = (uint32_t)((8 * h8 + l) * 36 + 4 * kh) * 4;
        uint32_t b_lo = (uint32_t)(9216 * 4) +
            (uint32_t)((8 * (m & 1) + l) * 12 + (m >> 1) * 4) * 4;
        uint32_t b_hi = (uint32_t)(9216 * 4) +
            (uint32_t)((8 * h8 + l) * 12 + 8) * 4;

        float acc3[2][4];
        #pragma unroll
        for (int nt = 0; nt < 2; ++nt) {
            int col = hi ? (16 + 2 * tg) : (8 * nt + 2 * tg);
            float b0 = (col < 18) ? __ldg(&ob[col]) : 0.f;
            float b1 = (col + 1 < 18) ? __ldg(&ob[col + 1]) : 0.f;
            acc3[nt][0] = b0; acc3[nt][1] = b1;
            acc3[nt][2] = b0; acc3[nt][3] = b1;
        }

        for (int ky = 0; ky < 3; ++ky) {
            int yy = y + ky - 1;
            if (yy < 0 || yy >= Hc) continue;   // uniform per block
            __syncthreads();
            uint4* xd = (uint4*)smw;
            #pragma unroll
            for (int i = 0; i < 3; ++i) {
                int j4 = tid + 512 * i;
                if (j4 < 1040) {
                    int xi = j4 >> 3, cg = j4 & 7, x = xi - 1;
                    uint4 v = make_uint4(0u, 0u, 0u, 0u);
                    if (x >= 0 && x < Wc)
                        v = g_xH4[((size_t)(b * Hc + yy) * Wc + x) * 8 + cg];
                    xd[xi * 9 + cg] = v;
                }
            }
            {
                uint4* od = (uint4*)(smw + 9216);
                #pragma unroll
                for (int i = 0; i < 2; ++i) {
                    int j4 = tid + 512 * i;
                    if (j4 < 576) od[j4] = g_owH4[ky * 576 + j4];
                }
            }
            __syncthreads();
            #pragma unroll
            for (int kx = 0; kx < 3; ++kx) {
                uint32_t abase = sb + (uint32_t)((amt * 16 + kx) * 36) * 4 + a_lane;
                #pragma unroll
                for (int kk = 0; kk < 4; ++kk) {
                    uint32_t a[4];
                    ldsm_x4(a, abase + kk * 32);
                    if (!hi) {
                        uint32_t bq[4];
                        ldsm_x4t(bq, sb + (uint32_t)(kx * 768) * 4 + b_lo + kk * 768);
                        mma16(acc3[0], a, bq[0], bq[1]);
                        mma16(acc3[1], a, bq[2], bq[3]);
                    } else {
                        uint32_t b2[2];
                        ldsm_x2t(b2, sb + (uint32_t)(kx * 768) * 4 + b_hi + kk * 768);
                        mma16(acc3[0], a, b2[0], b2[1]);
                    }
                }
            }
        }
        __syncthreads();
        float2* offs = (float2*)(smw + SM_OFFS);
        int p = amt * 16 + g;
        if (!hi) {
            #pragma unroll
            for (int nt = 0; nt < 2; ++nt) {
                int col = 8 * nt + 2 * tg;
                int tap = col >> 1;
                offs[tap * 128 + p]     = make_float2(acc3[nt][0], acc3[nt][1]);
                offs[tap * 128 + p + 8] = make_float2(acc3[nt][2], acc3[nt][3]);
            }
        } else if (tg == 0) {       // cols 16,17 = tap 8
            offs[8 * 128 + p]     = make_float2(acc3[0][0], acc3[0][1]);
            offs[8 * 128 + p + 8] = make_float2(acc3[0][2], acc3[0][3]);
        }
        __syncthreads();
    }

    // ======================= Phase B: main conv ============================
    int mgrp = warp >> 1, ngrp = warp & 1;     // 16px x 32co warp tile
    int s_cg = tid & 7, s_p0 = tid >> 3;       // 64 pixel slots
    const float2* offs = (const float2*)(smw + SM_OFFS);

    uint32_t a_lane = (uint32_t)((mgrp * 16 + 8 * h8 + l) * 36 + 4 * kh) * 4;
    uint32_t b_lane = (uint32_t)((8 * (m & 1) + l) * 36 +
                                 (ngrp * 4 + (m >> 1)) * 4) * 4;

    float acc[4][4];
    #pragma unroll
    for (int nt = 0; nt < 4; ++nt)
        #pragma unroll
        for (int j = 0; j < 4; ++j) acc[nt][j] = 0.f;

    // coords for tap 0 into coordbuf[0]
    if (tid < 128) {
        compute_coords(0, tid, y, b, offs,
                       (uint4*)(smw + SM_CB), (int4*)(smw + SM_CB + 512));
    }
    __syncthreads();

    for (int k = 0; k < 9; ++k) {
        int buf = k & 1;
        // stage weight tile via cp.async (overlaps sampling)
        {
            const uint4* src = g_wH4 + k * 512;
            uint32_t dbase = sb + (uint32_t)(9216 + buf * 2304) * 4;
            int c = tid >> 3, seg = tid & 7;
            cp_async16(dbase + (uint32_t)(c * 9 + seg) * 16, src + tid);
            CP_COMMIT();
        }
        // sample into patch[buf] using coordbuf[buf] — fp16 HFMA2 lerp
        {
            const uint4* cw = (const uint4*)(smw + SM_CB + buf * 1024);
            const int4*  ci = (const int4*)(smw + SM_CB + buf * 1024 + 512);
            uint4* pdst = (uint4*)(smw + buf * 4608);
            #pragma unroll
            for (int i = 0; i < 2; ++i) {
                int p = s_p0 + 64 * i;
                uint4 wq = cw[p];
                half2 w00h = ((half2*)&wq)[0];
                half2 w01h = ((half2*)&wq)[1];
                half2 w10h = ((half2*)&wq)[2];
                half2 w11h = ((half2*)&wq)[3];
                int4  c4 = ci[p];
                uint4 q00 = g_xH4[c4.x + s_cg];
                uint4 q01 = g_xH4[c4.y + s_cg];
                uint4 q10 = g_xH4[c4.z + s_cg];
                uint4 q11 = g_xH4[c4.w + s_cg];
                uint4 r;
                half2* hr = (half2*)&r;
                #pragma unroll
                for (int j = 0; j < 4; ++j) {
                    half2 t0 = __hfma2(((half2*)&q01)[j], w01h,
                                       __hmul2(((half2*)&q00)[j], w00h));
                    half2 t1 = __hfma2(((half2*)&q11)[j], w11h,
                                       __hmul2(((half2*)&q10)[j], w10h));
                    hr[j] = __hadd2(t0, t1);
                }
                pdst[p * 9 + s_cg] = r;
            }
        }
        // coords for tap k+1 into coordbuf[buf^1] (before barrier; read after)
        if (k < 8 && tid < 128) {
            compute_coords(k + 1, tid, y, b, offs,
                           (uint4*)(smw + SM_CB + (buf ^ 1) * 1024),
                           (int4*)(smw + SM_CB + (buf ^ 1) * 1024 + 512));
        }
        CP_WAIT0();
        __syncthreads();
        // GEMM via ldmatrix: 1 m-tile x 4 n-tiles per warp
        {
            uint32_t abase = sb + (uint32_t)(buf * 4608) * 4 + a_lane;
            uint32_t bbase = sb + (uint32_t)((9216 + buf * 2304)) * 4 + b_lane;
            #pragma unroll
            for (int kk = 0; kk < 4; ++kk) {
                uint32_t a0[4], bq0[4], bq1[4];
                ldsm_x4(a0, abase + kk * 32);
                ldsm_x4t(bq0, bbase + kk * 2304);
                ldsm_x4t(bq1, bbase + 32 + kk * 2304);
                mma16(acc[0], a0, bq0[0], bq0[1]);
                mma16(acc[1], a0, bq0[2], bq0[3]);
                mma16(acc[2], a0, bq1[0], bq1[1]);
                mma16(acc[3], a0, bq1[2], bq1[3]);
            }
        }
    }

    // epilogue: transpose through smem (stride 132 floats), add bias, store
    __syncthreads();
    float* O = (float*)smw;   // 64*132 = 8448 floats < 18176 words
    #pragma unroll
    for (int nt = 0; nt < 4; ++nt) {
        int row = mgrp * 16 + g;
        int col = ngrp * 32 + 8 * nt + 2 * tg;
        float b0 = __ldg(&bias[col]), b1 = __ldg(&bias[col + 1]);
        O[col * 132 + row]           = acc[nt][0] + b0;
        O[(col + 1) * 132 + row]     = acc[nt][1] + b1;
        O[col * 132 + row + 8]       = acc[nt][2] + b0;
        O[(col + 1) * 132 + row + 8] = acc[nt][3] + b1;
    }
    __syncthreads();
    #pragma unroll
    for (int i = 0; i < 4; ++i) {
        int j4 = tid + 512 * i;          // 2048 float4s
        int co = j4 >> 5, xq = j4 & 31;
        float4 v = *(float4*)&O[co * 132 + xq * 4];
        *(float4*)&out[(((size_t)b * COUTc + co) * Hc + y) * Wc + xq * 4] = v;
    }
}

// ---------------------------------------------------------------------------
extern "C" void kernel_launch(void* const* d_in, const int* in_sizes, int n_in,
                              void* d_out, int out_size)
{
    const float* x      = (const float*)d_in[0];
    const float* weight = (const float*)d_in[1];
    const float* bias   = (const float*)d_in[2];
    const float* ow     = (const float*)d_in[3];
    const float* ob     = (const float*)d_in[4];
    float* out = (float*)d_out;

    static int configured = 0;
    if (!configured) {
        cudaFuncSetAttribute(dcn_fused_kernel,
            cudaFuncAttributeMaxDynamicSharedMemorySize, 18176 * 4);
        configured = 1;
    }

    prep_kernel<<<512 + 36, 256>>>(x, weight, ow);
    dcn_fused_kernel<<<Bc * Hc, 512, 18176 * 4>>>(ob, bias, out);
}

// round 16
// speedup vs baseline: 1.1020x; 1.1020x over previous
#include <cuda_runtime.h>
#include <cuda_fp16.h>
#include <cstdint>

#define Hc 128
#define Wc 128
#define Cc 64
#define COUTc 64
#define Bc 4
#define NPIX (Bc*Hc*Wc)

// ------------------------------ scratch ------------------------------------
__device__ uint4  g_xH4[NPIX*8];        // NHWC fp16 input (8 uint4 = 64c/px)
__device__ uint4  g_wH4[9*512];         // main weights fp16 [tap][c64][co64]
__device__ uint4  g_owH4[9*192];        // offset weights fp16 [tap][c64][o24]

// ------------------------------ helpers ------------------------------------
__device__ __forceinline__ void mma16(float* d, const uint32_t* a,
                                      uint32_t b0, uint32_t b1) {
    asm volatile(
        "mma.sync.aligned.m16n8k16.row.col.f32.f16.f16.f32 "
        "{%0,%1,%2,%3}, {%4,%5,%6,%7}, {%8,%9}, {%0,%1,%2,%3};"
        : "+f"(d[0]), "+f"(d[1]), "+f"(d[2]), "+f"(d[3])
        : "r"(a[0]), "r"(a[1]), "r"(a[2]), "r"(a[3]), "r"(b0), "r"(b1));
}
__device__ __forceinline__ void ldsm_x4(uint32_t* r, uint32_t a) {
    asm volatile("ldmatrix.sync.aligned.m8n8.x4.shared.b16 {%0,%1,%2,%3}, [%4];"
        : "=r"(r[0]), "=r"(r[1]), "=r"(r[2]), "=r"(r[3]) : "r"(a));
}
__device__ __forceinline__ void ldsm_x4t(uint32_t* r, uint32_t a) {
    asm volatile("ldmatrix.sync.aligned.m8n8.x4.trans.shared.b16 {%0,%1,%2,%3}, [%4];"
        : "=r"(r[0]), "=r"(r[1]), "=r"(r[2]), "=r"(r[3]) : "r"(a));
}
__device__ __forceinline__ void ldsm_x2t(uint32_t* r, uint32_t a) {
    asm volatile("ldmatrix.sync.aligned.m8n8.x2.trans.shared.b16 {%0,%1}, [%2];"
        : "=r"(r[0]), "=r"(r[1]) : "r"(a));
}
__device__ __forceinline__ void cp_async16(uint32_t saddr, const void* gaddr) {
    asm volatile("cp.async.cg.shared.global [%0], [%1], 16;"
        :: "r"(saddr), "l"(gaddr) : "memory");
}
#define CP_COMMIT() asm volatile("cp.async.commit_group;" ::: "memory")
#define CP_WAIT0()  asm volatile("cp.async.wait_group 0;" ::: "memory")
#define HALF_BAR(id) asm volatile("bar.sync %0, 128;" :: "r"(id) : "memory")

// ---------------------------------------------------------------------------
// Kernel 1: prep. blocks 0..511: NCHW->NHWC fp16 transpose; 512+: weights.
// ---------------------------------------------------------------------------
__global__ void __launch_bounds__(256) prep_kernel(
    const float* __restrict__ x, const float* __restrict__ w,
    const float* __restrict__ ow)
{
    int bid = blockIdx.x, tid = threadIdx.x;
    if (bid < 512) {
        __shared__ float4 sm4[2048];
        int b = bid >> 7, y = bid & 127;
        const float4* xin = (const float4*)x;
        #pragma unroll
        for (int i = 0; i < 8; ++i) {
            int j4 = tid + 256 * i;
            int c = j4 >> 5, x4 = j4 & 31;
            int key = (c ^ (c >> 3)) & 7;
            sm4[c * 32 + (x4 ^ key)] =
                xin[((size_t)(b * Cc + c) * Hc + y) * 32 + x4];
        }
        __syncthreads();
        const float* smf = (const float*)sm4;
        #pragma unroll
        for (int i = 0; i < 4; ++i) {
            int j = tid + 256 * i;
            int grp = j & 7, px = j >> 3;
            float f[8];
            #pragma unroll
            for (int e = 0; e < 8; ++e) {
                int c = grp * 8 + e;
                int key = (c ^ (c >> 3)) & 7;
                f[e] = smf[c * 128 + 4 * ((px >> 2) ^ key) + (px & 3)];
            }
            uint4 r; half2* hr = (half2*)&r;
            hr[0] = __floats2half2_rn(f[0], f[1]);
            hr[1] = __floats2half2_rn(f[2], f[3]);
            hr[2] = __floats2half2_rn(f[4], f[5]);
            hr[3] = __floats2half2_rn(f[6], f[7]);
            g_xH4[((size_t)(b * Hc + y) * Wc + px) * 8 + grp] = r;
        }
    } else {
        int t = (bid - 512) * 256 + tid;
        half* wh = (half*)g_wH4;                    // [tap][c][co]
        for (int idx = t; idx < 9 * 64 * 64; idx += 36 * 256) {
            int tap = idx >> 12, r = idx & 4095;
            int c = r >> 6, co = r & 63;
            wh[idx] = __float2half(w[(co * Cc + c) * 9 + tap]);
        }
        half* oh = (half*)g_owH4;                   // [tap][c][24]
        for (int idx = t; idx < 9 * 64 * 24; idx += 36 * 256) {
            int tap = idx / 1536;
            int r = idx - tap * 1536;
            int c = r / 24, o = r - c * 24;
            oh[idx] = (o < 18) ? __float2half(ow[(o * Cc + c) * 9 + tap])
                               : __float2half(0.f);
        }
    }
}

// ---------------------------------------------------------------------------
// Kernel 2: FUSED offset conv + sampling + fp16 mma GEMM, SPLIT-HALF pipeline.
// Block = 1 image row (128 px) x 64 co, 256 threads, 3 blocks/SM.
// Phase B runs as TWO independent 128-thread halves (named barriers): half h
// owns pixels [64h, 64h+64) end-to-end (coords, sampling, GEMM m-rows), so
// halves slip past each other and cover gather latency. Weights are
// duplicate-staged (identical bytes) by both halves.
// smem words: patch[2][128][36] @0 (9216) | wsm[2][64][36] @9216 (4608)
//             offs[9][128]x2 @13824 (2304) | coordbuf[2][128]x8 @16128 (2048)
// total 18176 words = 72704 B
// ---------------------------------------------------------------------------
#define SM_OFFS 13824
#define SM_CB   16128
__device__ __forceinline__ void compute_coords(
    int k, int p, int y, int b, const float2* offs, uint4* cwh, int4* ci)
{
    float2 d2 = offs[k * 128 + p];
    int ky = k / 3, kx = k - ky * 3;
    float py  = (float)(y - 1 + ky) + d2.x;
    float pxx = (float)(p - 1 + kx) + d2.y;
    float fy = floorf(py), fx = floorf(pxx);
    float ly = py - fy, lx = pxx - fx;
    int y0 = (int)fy, xq = (int)fx;
    bool vy0 = (y0 >= 0) & (y0 < Hc);
    bool vy1 = (y0 + 1 >= 0) & (y0 + 1 < Hc);
    bool vx0 = (xq >= 0) & (xq < Wc);
    bool vx1 = (xq + 1 >= 0) & (xq + 1 < Wc);
    float w00 = (1.f - ly) * (1.f - lx) * (float)(vy0 && vx0);
    float w01 = (1.f - ly) * lx         * (float)(vy0 && vx1);
    float w10 = ly * (1.f - lx)         * (float)(vy1 && vx0);
    float w11 = ly * lx                 * (float)(vy1 && vx1);
    int yc0 = min(max(y0, 0), Hc - 1);
    int yc1 = min(max(y0 + 1, 0), Hc - 1);
    int xc0 = min(max(xq, 0), Wc - 1);
    int xc1 = min(max(xq + 1, 0), Wc - 1);
    int r0 = (b * Hc + yc0) * Wc, r1 = (b * Hc + yc1) * Wc;
    ci[p] = make_int4((r0 + xc0) * 8, (r0 + xc1) * 8,
                      (r1 + xc0) * 8, (r1 + xc1) * 8);
    uint4 wpk; half2* hp = (half2*)&wpk;
    hp[0] = __floats2half2_rn(w00, w00);
    hp[1] = __floats2half2_rn(w01, w01);
    hp[2] = __floats2half2_rn(w10, w10);
    hp[3] = __floats2half2_rn(w11, w11);
    cwh[p] = wpk;
}

__global__ void __launch_bounds__(256, 3) dcn_fused_kernel(
    const float* __restrict__ ob, const float* __restrict__ bias,
    float* __restrict__ out)
{
    extern __shared__ uint32_t smw[];
    uint32_t sb = (uint32_t)__cvta_generic_to_shared(smw);

    int tid = threadIdx.x, warp = tid >> 5, lane = tid & 31;
    int g = lane >> 2, tg = lane & 3;
    int l = lane & 7, h8 = (lane >> 3) & 1, kh = (lane >> 4) & 1;
    int m = lane >> 3;
    int blk = blockIdx.x, b = blk >> 7, y = blk & 127;

    // ======================= Phase A: offset conv ==========================
    {
        uint32_t a_lane = (uint32_t)((8 * h8 + l) * 36 + 4 * kh) * 4;
        uint32_t b_lane01 = (uint32_t)(9216 * 4) +
            (uint32_t)((8 * (m & 1) + l) * 12 + (m >> 1) * 4) * 4;
        uint32_t b_lane2  = (uint32_t)(9216 * 4) +
            (uint32_t)((8 * h8 + l) * 12 + 8) * 4;

        float acc3[3][4];
        #pragma unroll
        for (int nt = 0; nt < 3; ++nt) {
            int col = 8 * nt + 2 * tg;
            float b0 = (col < 18) ? __ldg(&ob[col]) : 0.f;
            float b1 = (col + 1 < 18) ? __ldg(&ob[col + 1]) : 0.f;
            acc3[nt][0] = b0; acc3[nt][1] = b1;
            acc3[nt][2] = b0; acc3[nt][3] = b1;
        }

        for (int ky = 0; ky < 3; ++ky) {
            int yy = y + ky - 1;
            if (yy < 0 || yy >= Hc) continue;   // uniform per block
            __syncthreads();
            uint4* xd = (uint4*)smw;
            #pragma unroll
            for (int i = 0; i < 5; ++i) {
                int j4 = tid + 256 * i;
                if (j4 < 1040) {
                    int xi = j4 >> 3, cg = j4 & 7, x = xi - 1;
                    uint4 v = make_uint4(0u, 0u, 0u, 0u);
                    if (x >= 0 && x < Wc)
                        v = g_xH4[((size_t)(b * Hc + yy) * Wc + x) * 8 + cg];
                    xd[xi * 9 + cg] = v;
                }
            }
            {
                uint4* od = (uint4*)(smw + 9216);
                #pragma unroll
                for (int i = 0; i < 3; ++i) {
                    int j4 = tid + 256 * i;
                    if (j4 < 576) od[j4] = g_owH4[ky * 576 + j4];
                }
            }
            __syncthreads();
            #pragma unroll
            for (int kx = 0; kx < 3; ++kx) {
                uint32_t abase = sb + (uint32_t)((warp * 16 + kx) * 36) * 4 + a_lane;
                uint32_t bb01  = sb + (uint32_t)(kx * 768) * 4 + b_lane01;
                uint32_t bb2   = sb + (uint32_t)(kx * 768) * 4 + b_lane2;
                #pragma unroll
                for (int kk = 0; kk < 4; ++kk) {
                    uint32_t a[4], bq[4], b2[2];
                    ldsm_x4(a, abase + kk * 32);
                    ldsm_x4t(bq, bb01 + kk * 768);
                    ldsm_x2t(b2, bb2 + kk * 768);
                    mma16(acc3[0], a, bq[0], bq[1]);
                    mma16(acc3[1], a, bq[2], bq[3]);
                    mma16(acc3[2], a, b2[0], b2[1]);
                }
            }
        }
        __syncthreads();
        float2* offs = (float2*)(smw + SM_OFFS);
        #pragma unroll
        for (int nt = 0; nt < 3; ++nt) {
            int col = 8 * nt + 2 * tg;
            if (col < 18) {
                int tap = col >> 1;
                int p = warp * 16 + g;
                offs[tap * 128 + p]     = make_float2(acc3[nt][0], acc3[nt][1]);
                offs[tap * 128 + p + 8] = make_float2(acc3[nt][2], acc3[nt][3]);
            }
        }
        __syncthreads();
    }

    // ============== Phase B: main conv, two independent halves =============
    int half = tid >> 7;            // 0 or 1: owns pixels [64*half, 64*half+64)
    int lt   = tid & 127;           // thread index within half
    int wl   = (tid >> 5) & 3;      // warp within half
    int barid = 1 + half;
    int mgrp = half * 2 + (wl >> 1);   // GEMM m-rows within own half
    int ngrp = wl & 1;
    int s_cg = tid & 7;
    int s_p0 = half * 64 + (lt >> 3);  // 16 pixel slots within own half
    const float2* offs = (const float2*)(smw + SM_OFFS);

    uint32_t a_lane = (uint32_t)((mgrp * 32 + 8 * h8 + l) * 36 + 4 * kh) * 4;
    uint32_t b_lane = (uint32_t)((8 * (m & 1) + l) * 36 +
                                 (ngrp * 4 + (m >> 1)) * 4) * 4;

    float acc[2][4][4];
    #pragma unroll
    for (int mt = 0; mt < 2; ++mt)
        #pragma unroll
        for (int nt = 0; nt < 4; ++nt)
            #pragma unroll
            for (int j = 0; j < 4; ++j) acc[mt][nt][j] = 0.f;

    // coords for tap 0 (own half's 64 pixels)
    if (lt < 64) {
        int p = half * 64 + lt;
        compute_coords(0, p, y, b, offs,
                       (uint4*)(smw + SM_CB), (int4*)(smw + SM_CB + 512));
    }
    HALF_BAR(barid);

    for (int k = 0; k < 9; ++k) {
        int buf = k & 1;
        // stage weight tile via cp.async — both halves write identical bytes
        {
            const uint4* src = g_wH4 + k * 512;
            uint32_t dbase = sb + (uint32_t)(9216 + buf * 2304) * 4;
            #pragma unroll
            for (int i = 0; i < 4; ++i) {
                int j4 = lt + 128 * i;
                int c = j4 >> 3, seg = j4 & 7;
                cp_async16(dbase + (uint32_t)(c * 9 + seg) * 16, src + j4);
            }
            CP_COMMIT();
        }
        // sample own half's pixels into patch[buf]
        {
            const uint4* cw = (const uint4*)(smw + SM_CB + buf * 1024);
            const int4*  ci = (const int4*)(smw + SM_CB + buf * 1024 + 512);
            uint4* pdst = (uint4*)(smw + buf * 4608);
            #pragma unroll
            for (int i = 0; i < 4; ++i) {
                int p = s_p0 + 16 * i;
                uint4 wq = cw[p];
                half2 w00h = ((half2*)&wq)[0];
                half2 w01h = ((half2*)&wq)[1];
                half2 w10h = ((half2*)&wq)[2];
                half2 w11h = ((half2*)&wq)[3];
                int4  c4 = ci[p];
                uint4 q00 = g_xH4[c4.x + s_cg];
                uint4 q01 = g_xH4[c4.y + s_cg];
                uint4 q10 = g_xH4[c4.z + s_cg];
                uint4 q11 = g_xH4[c4.w + s_cg];
                uint4 r;
                half2* hr = (half2*)&r;
                #pragma unroll
                for (int j = 0; j < 4; ++j) {
                    half2 t0 = __hfma2(((half2*)&q01)[j], w01h,
                                       __hmul2(((half2*)&q00)[j], w00h));
                    half2 t1 = __hfma2(((half2*)&q11)[j], w11h,
                                       __hmul2(((half2*)&q10)[j], w10h));
                    hr[j] = __hadd2(t0, t1);
                }
                pdst[p * 9 + s_cg] = r;
            }
        }
        // coords for tap k+1 (own half) into coordbuf[buf^1]
        if (k < 8 && lt < 64) {
            int p = half * 64 + lt;
            compute_coords(k + 1, p, y, b, offs,
                           (uint4*)(smw + SM_CB + (buf ^ 1) * 1024),
                           (int4*)(smw + SM_CB + (buf ^ 1) * 1024 + 512));
        }
        CP_WAIT0();
        HALF_BAR(barid);
        // GEMM via ldmatrix (own half's m-rows only)
        {
            uint32_t abase = sb + (uint32_t)(buf * 4608) * 4 + a_lane;
            uint32_t bbase = sb + (uint32_t)((9216 + buf * 2304)) * 4 + b_lane;
            #pragma unroll
            for (int kk = 0; kk < 4; ++kk) {
                uint32_t a0[4], a1[4], bq0[4], bq1[4];
                ldsm_x4(a0, abase + kk * 32);
                ldsm_x4(a1, abase + 2304 + kk * 32);
                ldsm_x4t(bq0, bbase + kk * 2304);
                ldsm_x4t(bq1, bbase + 32 + kk * 2304);
                mma16(acc[0][0], a0, bq0[0], bq0[1]);
                mma16(acc[0][1], a0, bq0[2], bq0[3]);
                mma16(acc[0][2], a0, bq1[0], bq1[1]);
                mma16(acc[0][3], a0, bq1[2], bq1[3]);
                mma16(acc[1][0], a1, bq0[0], bq0[1]);
                mma16(acc[1][1], a1, bq0[2], bq0[3]);
                mma16(acc[1][2], a1, bq1[0], bq1[1]);
                mma16(acc[1][3], a1, bq1[2], bq1[3]);
            }
        }
    }

    // epilogue: full sync (smem reuse), transpose, add bias, store NCHW
    __syncthreads();
    float* O = (float*)smw;
    #pragma unroll
    for (int mt = 0; mt < 2; ++mt)
        #pragma unroll
        for (int nt = 0; nt < 4; ++nt) {
            int row = mgrp * 32 + 16 * mt + g;
            int col = ngrp * 32 + 8 * nt + 2 * tg;
            float b0 = __ldg(&bias[col]), b1 = __ldg(&bias[col + 1]);
            O[col * 132 + row]           = acc[mt][nt][0] + b0;
            O[(col + 1) * 132 + row]     = acc[mt][nt][1] + b1;
            O[col * 132 + row + 8]       = acc[mt][nt][2] + b0;
            O[(col + 1) * 132 + row + 8] = acc[mt][nt][3] + b1;
        }
    __syncthreads();
    #pragma unroll
    for (int i = 0; i < 8; ++i) {
        int j4 = tid + 256 * i;
        int co = j4 >> 5, xq = j4 & 31;
        float4 v = *(float4*)&O[co * 132 + xq * 4];
        *(float4*)&out[(((size_t)b * COUTc + co) * Hc + y) * Wc + xq * 4] = v;
    }
}

// ---------------------------------------------------------------------------
extern "C" void kernel_launch(void* const* d_in, const int* in_sizes, int n_in,
                              void* d_out, int out_size)
{
    const float* x      = (const float*)d_in[0];
    const float* weight = (const float*)d_in[1];
    const float* bias   = (const float*)d_in[2];
    const float* ow     = (const float*)d_in[3];
    const float* ob     = (const float*)d_in[4];
    float* out = (float*)d_out;

    static int configured = 0;
    if (!configured) {
        cudaFuncSetAttribute(dcn_fused_kernel,
            cudaFuncAttributeMaxDynamicSharedMemorySize, 18176 * 4);
        configured = 1;
    }

    prep_kernel<<<512 + 36, 256>>>(x, weight, ow);
    dcn_fused_kernel<<<Bc * Hc, 256, 18176 * 4>>>(ob, bias, out);
}